// round 13
// baseline (speedup 1.0000x reference)
#include <cuda_runtime.h>
#include <cuda_bf16.h>

#define D_DIM     512
#define T_MASK    511
#define NTOK      1024
#define NTHREADS  256           // 8 warps = 2 tokens x 4 warps
#define TOK_PER_BLK 2
#define WPT       4             // warps per token
#define CHUNK     128           // dims per warp
#define NBLOCKS   (NTOK / TOK_PER_BLK)

// Device-global scratch (no allocations allowed).
__device__ float g_tokss[NTOK];
__device__ float g_scalar;

// fp32 sincos, args in [0, ~2.6e4]. k = a*2/pi fits in 15 bits, so the 2-term
// Cody-Waite with exact-product fmaf gives |r_err| <~ 1.2e-7. Immune to
// --use_fast_math (explicit fmaf/rintf).
__device__ __forceinline__ void sincos_fast(float a, float* s_out, float* c_out) {
    float kf = rintf(__fmul_rn(a, 0.63661977236758138f));   // 2/pi
    int   q  = (int)kf;
    float r  = fmaf(kf, -1.57079632679489662f, a);          // -float(pi/2)
    r        = fmaf(kf,  4.37113900018624283e-08f, r);      // -(pi/2 - C1f)
    float z  = __fmul_rn(r, r);

    float sp = 2.75573192e-06f;                             //  1/9!
    sp = fmaf(sp, z, -1.98412698e-04f);                     // -1/7!
    sp = fmaf(sp, z,  8.33333333e-03f);                     //  1/5!
    sp = fmaf(sp, z, -1.66666667e-01f);                     // -1/3!
    float sinr = fmaf(__fmul_rn(r, z), sp, r);

    float cp = -2.75573192e-07f;                            // -1/10!
    cp = fmaf(cp, z,  2.48015873e-05f);                     //  1/8!
    cp = fmaf(cp, z, -1.38888889e-03f);                     // -1/6!
    cp = fmaf(cp, z,  4.16666667e-02f);                     //  1/4!
    cp = fmaf(cp, z, -0.5f);
    float cosr = fmaf(cp, z, 1.0f);

    q &= 3;
    float sv, cv;
    if      (q == 0) { sv =  sinr; cv =  cosr; }
    else if (q == 1) { sv =  cosr; cv = -sinr; }
    else if (q == 2) { sv = -sinr; cv = -cosr; }
    else             { sv = -cosr; cv =  sinr; }
    *s_out = sv;
    *c_out = cv;
}

// 4 warps cooperate on one token; each warp owns a 128-dim chunk. Cross-warp
// combines go through small smem buffers (3 block barriers total; the
// normalized-embedding handoff is warp-local, so it needs only __syncwarp).
__global__ __launch_bounds__(NTHREADS)
void token_kernel(const int*   __restrict__ token_ids,
                  const float* __restrict__ resonances,
                  const float* __restrict__ emb_scales,
                  const float* __restrict__ emb_shifts,
                  const float* __restrict__ emb_norm,
                  const float* __restrict__ W_enc,   // [512,24] row-major
                  const float* __restrict__ b_enc,   // [24]
                  const float* __restrict__ W_dec,   // [24,512] row-major
                  const float* __restrict__ b_dec,   // [512]
                  const float* __restrict__ ecc_p,
                  const float* __restrict__ ep_p,
                  float*       __restrict__ out)
{
    __shared__ float s_emb[TOK_PER_BLK][WPT][CHUNK];
    __shared__ float s_ss[TOK_PER_BLK][WPT];
    __shared__ float s_part[TOK_PER_BLK][WPT][24];
    __shared__ float s_lr[TOK_PER_BLK][WPT];

    const int tid  = threadIdx.x;
    const int lane = tid & 31;
    const int wrp  = tid >> 5;          // 0..7
    const int tok  = wrp >> 2;          // 0..1
    const int wi   = wrp & 3;           // warp-in-token
    const int cb   = wi * CHUNK;        // chunk base dim
    const int bt   = blockIdx.x * TOK_PER_BLK + tok;

    const float ecc = ecc_p[0];
    const float ep  = ep_p[0];
    const float en  = emb_norm[0];

    // ---- embedding over this warp's 128 dims ----
    const int   t    = bt & T_MASK;
    const float tv   = __fdiv_rn((float)(token_ids[bt] % 1000000), 1000000.0f);
    const float base = __fadd_rn(tv, (float)t);

    float e[4];
    float ss = 0.0f;
#pragma unroll
    for (int i = 0; i < 4; i++) {
        int d = cb + lane + 32 * i;
        float ang = __fmul_rn(resonances[d], base);
        float s, c;
        sincos_fast(ang, &s, &c);
        float comp = __fadd_rn(__fmul_rn(c, __fadd_rn(1.0f, s)), __fmul_rn(s, s));
        float ev   = __fadd_rn(__fmul_rn(comp, emb_scales[d]), emb_shifts[d]);
        e[i] = ev;
        ss = fmaf(ev, ev, ss);
    }
#pragma unroll
    for (int o = 16; o; o >>= 1) ss += __shfl_xor_sync(0xffffffffu, ss, o);
    if (lane == 0) s_ss[tok][wi] = ss;
    __syncthreads();    // barrier 1: s_ss visible to all warps of this token

    // combine 4 partials (fixed order) -> token norm, normalize, stash in smem
    float sst = __fadd_rn(__fadd_rn(s_ss[tok][0], s_ss[tok][1]),
                          __fadd_rn(s_ss[tok][2], s_ss[tok][3]));
    float tn  = __fsqrt_rn(sst);
    float rcp = (tn > 0.0f) ? __fdiv_rn(en, tn) : 1.0f;
#pragma unroll
    for (int i = 0; i < 4; i++) {
        s_emb[tok][wi][lane + 32 * i] = __fmul_rn(e[i], rcp);
    }
    __syncwarp();       // warp-local handoff: encode reads only its own chunk

    // ---- encode: lane c<24 accumulates its column over this warp's rows ----
    // W_enc rows are 96B; 24 lanes read one row coalescedly (L1/L2-hot: all
    // 512 blocks reuse the same 48KB).
    {
        float pw = 0.0f;
        if (lane < 24) {
            const float* wp = W_enc + cb * 24 + lane;
#pragma unroll 8
            for (int r = 0; r < CHUNK; r++)
                pw = fmaf(s_emb[tok][wi][r], wp[r * 24], pw);
            s_part[tok][wi][lane] = pw;
        }
    }
    __syncthreads();    // barrier 2: s_part visible across the token's warps

    // ---- Golay section, redundantly per warp (all shuffle-local) ----
    float proj = 0.0f;
    if (lane < 24) {
        float p = __fadd_rn(__fadd_rn(s_part[tok][0][lane], s_part[tok][1][lane]),
                            __fadd_rn(s_part[tok][2][lane], s_part[tok][3][lane]));
        proj = __fadd_rn(p, b_enc[lane]);
    }

    // encode row k=lane(<12): g = sum_l bit(k,l)*proj[l], ascending l
    // golay_bit(k,l): l<12 -> l==k; l in [12,23) -> (k+l-12)%2; l==23 -> k%2.
    float g = 0.0f;
#pragma unroll
    for (int l = 0; l < 24; l++) {
        float pl = __shfl_sync(0xffffffffu, proj, l);
        bool bit = (l < 12) ? (l == lane)
                 : ((l < 23) ? (((lane + l - 12) & 1) != 0)
                             : ((lane & 1) != 0));
        if (bit) g = __fadd_rn(g, pl);
    }
    float lv = (lane < 12) ? __fmul_rn(rintf(__fdiv_rn(g, ecc)), ecc) : 0.0f;

    float eo = __fmul_rn(lv, lv);
#pragma unroll
    for (int o = 16; o; o >>= 1) eo += __shfl_xor_sync(0xffffffffu, eo, o);
    float e_out = __fsqrt_rn(eo);
    float r1  = __fdiv_rn(en, __fadd_rn(e_out, 1e-8f));   // e_in := emb_norm
    float lvs = __fmul_rn(__fmul_rn(lv, r1), ep);

    float ei2 = __fmul_rn(lvs, lvs);
#pragma unroll
    for (int o = 16; o; o >>= 1) ei2 += __shfl_xor_sync(0xffffffffu, ei2, o);
    float e_in2 = __fsqrt_rn(ei2);

    // decode col l=lane(<24): gd = sum_k bit(k,l)*lvs[k], then threshold
    float gd = 0.0f;
#pragma unroll
    for (int k = 0; k < 12; k++) {
        float lk = __shfl_sync(0xffffffffu, lvs, k);
        bool bit = (lane < 12) ? (lane == k)
                 : ((lane < 23) ? (((k + lane - 12) & 1) != 0)
                                : ((k & 1) != 0));
        if (bit) gd = __fadd_rn(gd, lk);
    }
    float corrv = (lane < 24 && fabsf(gd) > ecc) ? gd : 0.0f;
    float cr[24];
#pragma unroll
    for (int l = 0; l < 24; l++) cr[l] = __shfl_sync(0xffffffffu, corrv, l);

    // ---- res = corrected @ W_dec + b_dec over this warp's 128 dims ----
    float v0[2], v1[2];
    float lr = 0.0f;
#pragma unroll
    for (int i = 0; i < 2; i++) {
        int d0 = cb + 2 * lane + 64 * i;
        float a0 = 0.0f, a1 = 0.0f;
#pragma unroll
        for (int l = 0; l < 24; l++) {
            float2 w2 = *(const float2*)(W_dec + l * D_DIM + d0);
            a0 = fmaf(cr[l], w2.x, a0);
            a1 = fmaf(cr[l], w2.y, a1);
        }
        float2 b2 = *(const float2*)(b_dec + d0);
        a0 = __fadd_rn(a0, b2.x);
        a1 = __fadd_rn(a1, b2.y);
        v0[i] = a0; v1[i] = a1;
        lr = fmaf(a0, a0, fmaf(a1, a1, lr));
    }
#pragma unroll
    for (int o = 16; o; o >>= 1) lr += __shfl_xor_sync(0xffffffffu, lr, o);
    if (lane == 0) s_lr[tok][wi] = lr;
    __syncthreads();    // barrier 3: s_lr visible across the token's warps

    float lrt = __fadd_rn(__fadd_rn(s_lr[tok][0], s_lr[tok][1]),
                          __fadd_rn(s_lr[tok][2], s_lr[tok][3]));
    float e_out2 = __fsqrt_rn(lrt);
    float r2ep = __fmul_rn(__fdiv_rn(e_in2, __fadd_rn(e_out2, 1e-8f)), ep);

    // write unscaled res; ||res_token||^2 = (r2ep*e_out2)^2 (no reduction)
#pragma unroll
    for (int i = 0; i < 2; i++) {
        float2 o2;
        o2.x = __fmul_rn(v0[i], r2ep);
        o2.y = __fmul_rn(v1[i], r2ep);
        *(float2*)(out + bt * D_DIM + cb + 2 * lane + 64 * i) = o2;
    }
    if (wi == 0 && lane == 0) {
        float tnrm = __fmul_rn(r2ep, e_out2);
        g_tokss[bt] = __fmul_rn(tnrm, tnrm);
    }
}

// NOTE: _fractal_dimension cancels analytically: fd >= 1 (clip), out_energy =
// |fd| = fd => returned fd equals frac_norm * ||res||_F.
// So output = res * frac_norm * ||res||_F.
__global__ __launch_bounds__(256)
void finalize_kernel(const float* __restrict__ frac_norm) {
    __shared__ float sbuf[8];
    int lane = threadIdx.x & 31, w = threadIdx.x >> 5;
    float v = 0.0f;
#pragma unroll
    for (int k = 0; k < NTOK / 256; k++)
        v = __fadd_rn(v, g_tokss[threadIdx.x + k * 256]);
#pragma unroll
    for (int o = 16; o; o >>= 1) v += __shfl_xor_sync(0xffffffffu, v, o);
    if (lane == 0) sbuf[w] = v;
    __syncthreads();
    if (threadIdx.x == 0) {
        float tot = 0.0f;
#pragma unroll
        for (int i = 0; i < 8; i++) tot = __fadd_rn(tot, sbuf[i]);
        g_scalar = __fmul_rn(frac_norm[0], __fsqrt_rn(tot));
    }
}

__global__ void scale_kernel(float4* __restrict__ out, int n4) {
    int i = blockIdx.x * blockDim.x + threadIdx.x;
    if (i < n4) {
        float s = g_scalar;
        float4 v = out[i];
        v.x = __fmul_rn(v.x, s);
        v.y = __fmul_rn(v.y, s);
        v.z = __fmul_rn(v.z, s);
        v.w = __fmul_rn(v.w, s);
        out[i] = v;
    }
}

extern "C" void kernel_launch(void* const* d_in, const int* in_sizes, int n_in,
                              void* d_out, int out_size) {
    const int*   token_ids  = (const int*)  d_in[0];
    const float* resonances = (const float*)d_in[1];
    const float* emb_scales = (const float*)d_in[2];
    const float* emb_shifts = (const float*)d_in[3];
    const float* emb_norm   = (const float*)d_in[4];
    // d_in[5] scale_weights, d_in[6] fractal_bias: provably unused (fd cancels)
    const float* frac_norm  = (const float*)d_in[7];
    const float* W_enc      = (const float*)d_in[8];
    const float* b_enc      = (const float*)d_in[9];
    const float* W_dec      = (const float*)d_in[10];
    const float* b_dec      = (const float*)d_in[11];
    const float* ecc        = (const float*)d_in[12];
    const float* ep         = (const float*)d_in[13];
    float* out = (float*)d_out;

    token_kernel<<<NBLOCKS, NTHREADS>>>(token_ids, resonances, emb_scales,
                                        emb_shifts, emb_norm, W_enc, b_enc,
                                        W_dec, b_dec, ecc, ep, out);
    finalize_kernel<<<1, 256>>>(frac_norm);
    const int n4 = (NTOK * D_DIM) / 4;
    scale_kernel<<<(n4 + 255) / 256, 256>>>((float4*)out, n4);
}

// round 14
// speedup vs baseline: 1.5009x; 1.5009x over previous
#include <cuda_runtime.h>
#include <cuda_bf16.h>

#define D_DIM     512
#define T_MASK    511
#define NTOK      1024
#define NTHREADS  256

// Device-global scratch (no allocations allowed).
__device__ float g_wencT[24 * D_DIM];   // W_enc transposed: [24][512]
__device__ float g_tokss[NTOK];
__device__ float g_scalar;

// fp32 sincos, args in [0, ~2.6e4]. k = a*2/pi fits in 15 bits, so the 2-term
// Cody-Waite with exact-product fmaf gives |r_err| <~ 1.2e-7. Immune to
// --use_fast_math (explicit fmaf/rintf).
__device__ __forceinline__ void sincos_fast(float a, float* s_out, float* c_out) {
    float kf = rintf(__fmul_rn(a, 0.63661977236758138f));   // 2/pi
    int   q  = (int)kf;
    float r  = fmaf(kf, -1.57079632679489662f, a);          // -float(pi/2)
    r        = fmaf(kf,  4.37113900018624283e-08f, r);      // -(pi/2 - C1f)
    float z  = __fmul_rn(r, r);

    float sp = 2.75573192e-06f;                             //  1/9!
    sp = fmaf(sp, z, -1.98412698e-04f);                     // -1/7!
    sp = fmaf(sp, z,  8.33333333e-03f);                     //  1/5!
    sp = fmaf(sp, z, -1.66666667e-01f);                     // -1/3!
    float sinr = fmaf(__fmul_rn(r, z), sp, r);

    float cp = -2.75573192e-07f;                            // -1/10!
    cp = fmaf(cp, z,  2.48015873e-05f);                     //  1/8!
    cp = fmaf(cp, z, -1.38888889e-03f);                     // -1/6!
    cp = fmaf(cp, z,  4.16666667e-02f);                     //  1/4!
    cp = fmaf(cp, z, -0.5f);
    float cosr = fmaf(cp, z, 1.0f);

    q &= 3;
    float sv, cv;
    if      (q == 0) { sv =  sinr; cv =  cosr; }
    else if (q == 1) { sv =  cosr; cv = -sinr; }
    else if (q == 2) { sv = -sinr; cv = -cosr; }
    else             { sv = -cosr; cv =  sinr; }
    *s_out = sv;
    *c_out = cv;
}

// One-wave transpose of W_enc [512,24] -> g_wencT [24,512].
// Coalesced reads; scattered 4B writes are fire-and-forget.
__global__ void transpose_kernel(const float* __restrict__ W_enc) {
    int i = blockIdx.x * blockDim.x + threadIdx.x;   // 0..12287
    int d = i / 24, c = i % 24;
    g_wencT[c * D_DIM + d] = W_enc[i];
}

// Block per token, 256 threads, single wave (1024 blocks ~ 7/SM).
__global__ __launch_bounds__(NTHREADS)
void token_kernel(const int*   __restrict__ token_ids,
                  const float* __restrict__ resonances,
                  const float* __restrict__ emb_scales,
                  const float* __restrict__ emb_shifts,
                  const float* __restrict__ emb_norm,
                  const float* __restrict__ b_enc,   // [24]
                  const float* __restrict__ W_dec,   // [24,512] row-major
                  const float* __restrict__ b_dec,   // [512]
                  const float* __restrict__ ecc_p,
                  const float* __restrict__ ep_p,
                  float*       __restrict__ out)
{
    __shared__ float s_emb[D_DIM];
    __shared__ float s_ss[8];
    __shared__ float s_proj[24];
    __shared__ float s_latt[12];
    __shared__ float s_corr[24];
    __shared__ float s_lr[8];
    __shared__ float s_sc;

    const int bt   = blockIdx.x;
    const int tid  = threadIdx.x;
    const int lane = tid & 31;
    const int w    = tid >> 5;

    const float ecc = ecc_p[0];
    const float ep  = ep_p[0];
    const float en  = emb_norm[0];

    // ---- phase 1: embedding (2 dims/thread) + per-warp sumsq ----
    const int   t    = bt & T_MASK;
    const float tv   = __fdiv_rn((float)(token_ids[bt] % 1000000), 1000000.0f);
    const float base = __fadd_rn(tv, (float)t);

    const int d0 = tid, d1 = tid + NTHREADS;
    float s0, c0s, s1, c1s;
    sincos_fast(__fmul_rn(resonances[d0], base), &s0, &c0s);
    sincos_fast(__fmul_rn(resonances[d1], base), &s1, &c1s);
    float e0 = __fadd_rn(__fmul_rn(__fadd_rn(__fmul_rn(c0s, __fadd_rn(1.0f, s0)),
                                             __fmul_rn(s0, s0)),
                                   emb_scales[d0]), emb_shifts[d0]);
    float e1 = __fadd_rn(__fmul_rn(__fadd_rn(__fmul_rn(c1s, __fadd_rn(1.0f, s1)),
                                             __fmul_rn(s1, s1)),
                                   emb_scales[d1]), emb_shifts[d1]);
    float ss = fmaf(e0, e0, __fmul_rn(e1, e1));
#pragma unroll
    for (int o = 16; o; o >>= 1) ss += __shfl_xor_sync(0xffffffffu, ss, o);
    if (lane == 0) s_ss[w] = ss;
    __syncthreads();                       // barrier 1

    // ---- phase 2: combine (fixed order), normalize into smem ----
    float sst = __fadd_rn(
        __fadd_rn(__fadd_rn(s_ss[0], s_ss[1]), __fadd_rn(s_ss[2], s_ss[3])),
        __fadd_rn(__fadd_rn(s_ss[4], s_ss[5]), __fadd_rn(s_ss[6], s_ss[7])));
    float tn  = __fsqrt_rn(sst);
    float rcp = (tn > 0.0f) ? __fdiv_rn(en, tn) : 1.0f;
    s_emb[d0] = __fmul_rn(e0, rcp);
    s_emb[d1] = __fmul_rn(e1, rcp);
    __syncthreads();                       // barrier 2

    // ---- phase 3: encode — warp w owns columns 3w..3w+2 of W_enc^T ----
    // Lane loads 16 emb values (stride-32 LDS, conflict-free); 3 independent
    // 16-FMA chains with coalesced LDGs from g_wencT (L1/L2-hot).
    {
        float em[16];
#pragma unroll
        for (int j = 0; j < 16; j++) em[j] = s_emb[lane + 32 * j];
        const int cbase = 3 * w;
        const float* wt0 = g_wencT + (cbase + 0) * D_DIM;
        const float* wt1 = g_wencT + (cbase + 1) * D_DIM;
        const float* wt2 = g_wencT + (cbase + 2) * D_DIM;
        float p0 = 0.0f, p1 = 0.0f, p2 = 0.0f;
#pragma unroll
        for (int j = 0; j < 16; j++) {
            int d = lane + 32 * j;
            p0 = fmaf(em[j], wt0[d], p0);
            p1 = fmaf(em[j], wt1[d], p1);
            p2 = fmaf(em[j], wt2[d], p2);
        }
#pragma unroll
        for (int o = 16; o; o >>= 1) {
            p0 += __shfl_xor_sync(0xffffffffu, p0, o);
            p1 += __shfl_xor_sync(0xffffffffu, p1, o);
            p2 += __shfl_xor_sync(0xffffffffu, p2, o);
        }
        if (lane == 0) {
            s_proj[cbase]     = __fadd_rn(p0, b_enc[cbase]);
            s_proj[cbase + 1] = __fadd_rn(p1, b_enc[cbase + 1]);
            s_proj[cbase + 2] = __fadd_rn(p2, b_enc[cbase + 2]);
        }
    }
    __syncthreads();                       // barrier 3

    // ---- phase 4: Golay on warp 0 only (LDS broadcasts, short chains) ----
    // golay_bit(k,l): l<12 -> l==k; l in [12,23) -> (k+l-12)%2; l==23 -> k%2.
    if (w == 0) {
        float lv = 0.0f;
        if (lane < 12) {
            float g = 0.0f;
#pragma unroll
            for (int l = 0; l < 24; l++) {
                bool bit = (l < 12) ? (l == lane)
                         : ((l < 23) ? (((lane + l - 12) & 1) != 0)
                                     : ((lane & 1) != 0));
                if (bit) g = __fadd_rn(g, s_proj[l]);
            }
            lv = __fmul_rn(rintf(__fdiv_rn(g, ecc)), ecc);   // half-to-even
        }
        float eo = __fmul_rn(lv, lv);
#pragma unroll
        for (int o = 16; o; o >>= 1) eo += __shfl_xor_sync(0xffffffffu, eo, o);
        float e_out = __fsqrt_rn(eo);
        float r1  = __fdiv_rn(en, __fadd_rn(e_out, 1e-8f));  // e_in := emb_norm
        float lvs = __fmul_rn(__fmul_rn(lv, r1), ep);

        float ei2 = __fmul_rn(lvs, lvs);
#pragma unroll
        for (int o = 16; o; o >>= 1) ei2 += __shfl_xor_sync(0xffffffffu, ei2, o);

        if (lane < 12) s_latt[lane] = lvs;
        if (lane == 0) s_sc = __fsqrt_rn(ei2);               // e_in2
        __syncwarp();

        if (lane < 24) {
            float gd = 0.0f;
#pragma unroll
            for (int k = 0; k < 12; k++) {
                bool bit = (lane < 12) ? (lane == k)
                         : ((lane < 23) ? (((k + lane - 12) & 1) != 0)
                                        : ((k & 1) != 0));
                if (bit) gd = __fadd_rn(gd, s_latt[k]);
            }
            s_corr[lane] = (fabsf(gd) > ecc) ? gd : 0.0f;
        }
    }
    __syncthreads();                       // barrier 4

    // ---- phase 5: decode (coalesced W_dec), renorm, write ----
    float cr[24];
#pragma unroll
    for (int l = 0; l < 24; l++) cr[l] = s_corr[l];

    float a0 = 0.0f, a1 = 0.0f;
#pragma unroll
    for (int l = 0; l < 24; l++) {
        a0 = fmaf(cr[l], W_dec[l * D_DIM + d0], a0);
        a1 = fmaf(cr[l], W_dec[l * D_DIM + d1], a1);
    }
    a0 = __fadd_rn(a0, b_dec[d0]);
    a1 = __fadd_rn(a1, b_dec[d1]);

    float lr = fmaf(a0, a0, __fmul_rn(a1, a1));
#pragma unroll
    for (int o = 16; o; o >>= 1) lr += __shfl_xor_sync(0xffffffffu, lr, o);
    if (lane == 0) s_lr[w] = lr;
    __syncthreads();                       // barrier 5

    float lrt = __fadd_rn(
        __fadd_rn(__fadd_rn(s_lr[0], s_lr[1]), __fadd_rn(s_lr[2], s_lr[3])),
        __fadd_rn(__fadd_rn(s_lr[4], s_lr[5]), __fadd_rn(s_lr[6], s_lr[7])));
    float e_out2 = __fsqrt_rn(lrt);
    float r2ep = __fmul_rn(__fdiv_rn(s_sc, __fadd_rn(e_out2, 1e-8f)), ep);

    out[bt * D_DIM + d0] = __fmul_rn(a0, r2ep);
    out[bt * D_DIM + d1] = __fmul_rn(a1, r2ep);

    // ||res_token||^2 = (r2ep * e_out2)^2 — no reduction needed
    if (tid == 0) {
        float tnrm = __fmul_rn(r2ep, e_out2);
        g_tokss[bt] = __fmul_rn(tnrm, tnrm);
    }
}

// NOTE: _fractal_dimension cancels analytically: fd >= 1 (clip), out_energy =
// |fd| = fd => returned fd equals frac_norm * ||res||_F.
// So output = res * frac_norm * ||res||_F.
__global__ __launch_bounds__(256)
void finalize_kernel(const float* __restrict__ frac_norm) {
    __shared__ float sbuf[8];
    int lane = threadIdx.x & 31, w = threadIdx.x >> 5;
    float v = 0.0f;
#pragma unroll
    for (int k = 0; k < NTOK / 256; k++)
        v = __fadd_rn(v, g_tokss[threadIdx.x + k * 256]);
#pragma unroll
    for (int o = 16; o; o >>= 1) v += __shfl_xor_sync(0xffffffffu, v, o);
    if (lane == 0) sbuf[w] = v;
    __syncthreads();
    if (threadIdx.x == 0) {
        float tot = 0.0f;
#pragma unroll
        for (int i = 0; i < 8; i++) tot = __fadd_rn(tot, sbuf[i]);
        g_scalar = __fmul_rn(frac_norm[0], __fsqrt_rn(tot));
    }
}

__global__ void scale_kernel(float4* __restrict__ out, int n4) {
    int i = blockIdx.x * blockDim.x + threadIdx.x;
    if (i < n4) {
        float s = g_scalar;
        float4 v = out[i];
        v.x = __fmul_rn(v.x, s);
        v.y = __fmul_rn(v.y, s);
        v.z = __fmul_rn(v.z, s);
        v.w = __fmul_rn(v.w, s);
        out[i] = v;
    }
}

extern "C" void kernel_launch(void* const* d_in, const int* in_sizes, int n_in,
                              void* d_out, int out_size) {
    const int*   token_ids  = (const int*)  d_in[0];
    const float* resonances = (const float*)d_in[1];
    const float* emb_scales = (const float*)d_in[2];
    const float* emb_shifts = (const float*)d_in[3];
    const float* emb_norm   = (const float*)d_in[4];
    // d_in[5] scale_weights, d_in[6] fractal_bias: provably unused (fd cancels)
    const float* frac_norm  = (const float*)d_in[7];
    const float* W_enc      = (const float*)d_in[8];
    const float* b_enc      = (const float*)d_in[9];
    const float* W_dec      = (const float*)d_in[10];
    const float* b_dec      = (const float*)d_in[11];
    const float* ecc        = (const float*)d_in[12];
    const float* ep         = (const float*)d_in[13];
    float* out = (float*)d_out;

    transpose_kernel<<<48, 256>>>(W_enc);
    token_kernel<<<NTOK, NTHREADS>>>(token_ids, resonances, emb_scales,
                                     emb_shifts, emb_norm, b_enc,
                                     W_dec, b_dec, ecc, ep, out);
    finalize_kernel<<<1, 256>>>(frac_norm);
    const int n4 = (NTOK * D_DIM) / 4;
    scale_kernel<<<(n4 + 255) / 256, 256>>>((float4*)out, n4);
}